// round 10
// baseline (speedup 1.0000x reference)
#include <cuda_runtime.h>
#include <cstdint>

#define NN 50000
#define CE 800000
#define C  128
#define NT 64
#define NTILES 782               // ceil(50000/64)
#define GRID_G 304               // 2 CTAs per SM * 152 SMs
#define S 132                    // smem row stride (floats), 132%32=4
#define SW_FL (128*S)            // 16896 floats
#define SX_FL (NT*S)             // 8448 floats
#define SMEM_B ((SW_FL+SX_FL)*4) // 101376 bytes -> 2 CTAs/SM
#define SCAN_BLOCKS 196          // 196*256 = 50176 >= NN

// scratch (allocation-free rule: __device__ globals)
__device__ __align__(16) float g_h[(size_t)NN * C];
__device__ __align__(16) float g_agg[(size_t)NN * C];
__device__ __align__(16) float g_y[(size_t)NN * C];

// CSR
__device__ int g_deg[NN];
__device__ int g_row[NN];
__device__ int g_cur[NN];
__device__ int g_srcs[CE];
__device__ int g_bsum[256];
__device__ int g_boff[256];

// per-launch GEMM tile counters (reset in zero_deg_kernel each call)
__device__ int g_tctr[16];

// dtype flags resolved on-device
__device__ int g_ei_is64;
__device__ int g_mask_is4B;

// ---------------------------------------------------------------------------
__global__ void sniff_kernel(const void* ei, const void* m0) {
    if (blockIdx.x != 0 || threadIdx.x != 0) return;
    const long long* e64 = (const long long*)ei;
    int is64 = 1;
    for (int i = 0; i < 256; i++) {
        long long v = e64[i];
        if (v < 0 || v >= NN) { is64 = 0; break; }
    }
    g_ei_is64 = is64;
    const unsigned* mu = (const unsigned*)m0;
    int is4B = 1;
    for (int i = 0; i < 256; i++) {
        unsigned v = mu[i];
        if (v != 0u && v != 1u && v != 0x3F800000u) { is4B = 0; break; }
    }
    g_mask_is4B = is4B;
}

__device__ __forceinline__ uint4 load_mask4(const void* m, size_t idx4, int m4B) {
    if (m4B) { const uint4 v = ((const uint4*)m)[idx4]; return make_uint4(v.x, v.y, v.z, v.w); }
    const uchar4 v = ((const uchar4*)m)[idx4];
    return make_uint4(v.x, v.y, v.z, v.w);
}
__device__ __forceinline__ uint2 load_mask2(const void* m, size_t off, int m4B) {
    if (m4B) return *(const uint2*)((const unsigned*)m + off);
    const unsigned char* p = (const unsigned char*)m + off;
    return make_uint2(p[0], p[1]);
}
__device__ __forceinline__ float tf32r(float f) {
    uint32_t r;
    asm("cvt.rna.tf32.f32 %0, %1;" : "=r"(r) : "f"(f));
    return __uint_as_float(r);
}
__device__ __forceinline__ void edge_sd(const void* ei, unsigned e, unsigned& s, unsigned& d) {
    if (g_ei_is64) {
        s = (unsigned)((const long long*)ei)[e];
        d = (unsigned)((const long long*)ei)[CE + e];
    } else {
        s = (unsigned)((const int*)ei)[e];
        d = (unsigned)((const int*)ei)[CE + e];
    }
}

// ---------------------------------------------------------------------------
// h = dropout(x) rounded to tf32
// ---------------------------------------------------------------------------
__global__ void init_kernel(const float* __restrict__ x, const void* __restrict__ d0) {
    const int m4B = g_mask_is4B;
    size_t i = (size_t)blockIdx.x * blockDim.x + threadIdx.x;
    if (i >= (size_t)NN * (C / 4)) return;
    float4 v = reinterpret_cast<const float4*>(x)[i];
    uint4 m = load_mask4(d0, i, m4B);
    float4 r;
    r.x = m.x ? tf32r(v.x * 2.5f) : 0.0f;
    r.y = m.y ? tf32r(v.y * 2.5f) : 0.0f;
    r.z = m.z ? tf32r(v.z * 2.5f) : 0.0f;
    r.w = m.w ? tf32r(v.w * 2.5f) : 0.0f;
    reinterpret_cast<float4*>(g_h)[i] = r;
}

// ---------------------------------------------------------------------------
// CSR build
// ---------------------------------------------------------------------------
__global__ void zero_deg_kernel() {
    int i = blockIdx.x * blockDim.x + threadIdx.x;
    if (i < NN) g_deg[i] = 0;
    if (blockIdx.x == 0 && threadIdx.x < 16) g_tctr[threadIdx.x] = 0;
}
__global__ void hist_kernel(const void* __restrict__ ei) {
    unsigned e = blockIdx.x * blockDim.x + threadIdx.x;
    if (e >= CE) return;
    unsigned s, d;
    edge_sd(ei, e, s, d);
    if (s >= NN || d >= NN) return;
    atomicAdd(&g_deg[d], 1);
}
__global__ void scan_block_kernel() {
    __shared__ int sd[256];
    const int tx = threadIdx.x;
    int idx = blockIdx.x * 256 + tx;
    int d = (idx < NN) ? g_deg[idx] : 0;
    int val = d;
    sd[tx] = val;
    __syncthreads();
    #pragma unroll
    for (int off = 1; off < 256; off <<= 1) {
        int t = (tx >= off) ? sd[tx - off] : 0;
        __syncthreads();
        val += t;
        sd[tx] = val;
        __syncthreads();
    }
    if (idx < NN) g_row[idx] = val - d;
    if (tx == 255) g_bsum[blockIdx.x] = val;
}
__global__ void scan_tops_kernel() {
    __shared__ int sd[256];
    const int tx = threadIdx.x;
    int d = (tx < SCAN_BLOCKS) ? g_bsum[tx] : 0;
    int val = d;
    sd[tx] = val;
    __syncthreads();
    #pragma unroll
    for (int off = 1; off < 256; off <<= 1) {
        int t = (tx >= off) ? sd[tx - off] : 0;
        __syncthreads();
        val += t;
        sd[tx] = val;
        __syncthreads();
    }
    g_boff[tx] = val - d;
}
__global__ void scan_fix_kernel() {
    int idx = blockIdx.x * 256 + threadIdx.x;
    if (idx >= NN) return;
    int r = g_row[idx] + g_boff[blockIdx.x];
    g_row[idx] = r;
    g_cur[idx] = r;
}
__global__ void fill_kernel(const void* __restrict__ ei) {
    unsigned e = blockIdx.x * blockDim.x + threadIdx.x;
    if (e >= CE) return;
    unsigned s, d;
    edge_sd(ei, e, s, d);
    if (s >= NN || d >= NN) return;
    int p = atomicAdd(&g_cur[d], 1);
    g_srcs[p] = (int)s;
}

// ---------------------------------------------------------------------------
// Gather-reduce: agg[n] = tf32(sum_{j in N(n)} h[j]). Warp per node.
// Pre-rounds to tf32 so the GEMM can consume raw bits (no in-loop cvt).
// ---------------------------------------------------------------------------
__global__ void __launch_bounds__(256)
gather_kernel() {
    unsigned w = (blockIdx.x * blockDim.x + threadIdx.x) >> 5;
    if (w >= NN) return;
    const int lane = threadIdx.x & 31;
    const int start = g_row[w];
    const int deg = g_deg[w];
    float4 a0 = make_float4(0.f, 0.f, 0.f, 0.f), a1 = a0, a2 = a0, a3 = a0;
    int j = 0;
    for (; j + 4 <= deg; j += 4) {
        int s0 = g_srcs[start + j + 0];
        int s1 = g_srcs[start + j + 1];
        int s2 = g_srcs[start + j + 2];
        int s3 = g_srcs[start + j + 3];
        float4 v0 = reinterpret_cast<const float4*>(g_h + (size_t)s0 * C)[lane];
        float4 v1 = reinterpret_cast<const float4*>(g_h + (size_t)s1 * C)[lane];
        float4 v2 = reinterpret_cast<const float4*>(g_h + (size_t)s2 * C)[lane];
        float4 v3 = reinterpret_cast<const float4*>(g_h + (size_t)s3 * C)[lane];
        a0.x += v0.x; a0.y += v0.y; a0.z += v0.z; a0.w += v0.w;
        a1.x += v1.x; a1.y += v1.y; a1.z += v1.z; a1.w += v1.w;
        a2.x += v2.x; a2.y += v2.y; a2.z += v2.z; a2.w += v2.w;
        a3.x += v3.x; a3.y += v3.y; a3.z += v3.z; a3.w += v3.w;
    }
    for (; j < deg; j++) {
        int s0 = g_srcs[start + j];
        float4 v0 = reinterpret_cast<const float4*>(g_h + (size_t)s0 * C)[lane];
        a0.x += v0.x; a0.y += v0.y; a0.z += v0.z; a0.w += v0.w;
    }
    float4 r;
    r.x = tf32r((a0.x + a1.x) + (a2.x + a3.x));
    r.y = tf32r((a0.y + a1.y) + (a2.y + a3.y));
    r.z = tf32r((a0.z + a1.z) + (a2.z + a3.z));
    r.w = tf32r((a0.w + a1.w) + (a2.w + a3.w));
    reinterpret_cast<float4*>(g_agg + (size_t)w * C)[lane] = r;
}

// ---------------------------------------------------------------------------
// Half-K GEMM (K=128), tf32 mma.sync, persistent with atomic tile stealing,
// cp.async-pipelined. Operands are pre-rounded tf32 -> raw bit loads.
// MODE 0 (root):    g_y  = X(h)·W^T + bias
// MODE 1 (combine): g_h  = tf32(drop(relu(X(agg)·W^T + Y)))
// MODE 2 (final):   out  = X(agg)·W^T + Y
// ---------------------------------------------------------------------------
template <int MODE>
__global__ void __launch_bounds__(256, 2)
gemm_half(const float* __restrict__ W, const float* __restrict__ bias,
          const void* __restrict__ drop, const float* __restrict__ Xsrc,
          float* __restrict__ outp, int cid) {
    extern __shared__ float sm[];
    float* sW = sm;
    float* sX = sm + SW_FL;
    __shared__ int sTile;

    const int tid = threadIdx.x;
    const int m4B = g_mask_is4B;

    #pragma unroll 4
    for (int j = tid; j < 128 * 32; j += 256) {
        int o = j >> 5, kq = j & 31;
        float4 v = ((const float4*)W)[j];
        float4 t = make_float4(tf32r(v.x), tf32r(v.y), tf32r(v.z), tf32r(v.w));
        *(float4*)(sW + o * S + kq * 4) = t;
    }

    uint32_t sXaddr;
    asm("{.reg .u64 t; cvta.to.shared.u64 t, %1; cvt.u32.u64 %0, t;}"
        : "=r"(sXaddr) : "l"(sX));

    const int wid = tid >> 5, lane = tid & 31;
    const int warpM = wid & 1, warpN = wid >> 1;
    const int lr = lane >> 2, lc = lane & 3;

    float2 bias2[4];
    if (MODE == 0) {
        #pragma unroll
        for (int nf = 0; nf < 4; nf++)
            bias2[nf] = *(const float2*)(bias + warpN * 32 + nf * 8 + lc * 2);
    }

    // grab + prefetch first tile
    if (tid == 0) sTile = atomicAdd(&g_tctr[cid], 1);
    __syncthreads();
    int cur = sTile;
    if (cur < NTILES) {
        #pragma unroll
        for (int j = 0; j < 8; j++) {
            int idx = tid + j * 256;
            int row = idx & 63, ch = idx >> 6;
            int node = cur * NT + row;
            const float* src = Xsrc + (size_t)(node < NN ? node : 0) * C + ch * 4;
            int sz = (node < NN) ? 16 : 0;
            asm volatile("cp.async.cg.shared.global [%0], [%1], 16, %2;"
                         :: "r"(sXaddr + (unsigned)(row * S + ch * 4) * 4), "l"(src), "r"(sz));
        }
    }
    asm volatile("cp.async.commit_group;" ::: "memory");

    while (cur < NTILES) {
        asm volatile("cp.async.wait_group 0;" ::: "memory");
        __syncthreads();

        float d[2][4][4];
        #pragma unroll
        for (int mf = 0; mf < 2; mf++)
            #pragma unroll
            for (int nf = 0; nf < 4; nf++)
                #pragma unroll
                for (int j = 0; j < 4; j++) d[mf][nf][j] = 0.0f;

        #pragma unroll 8
        for (int ks = 0; ks < 16; ks++) {
            const int kb = ks * 8;
            uint32_t a[2][4], bb[4][2];
            #pragma unroll
            for (int mf = 0; mf < 2; mf++) {
                const float* p = sX + (warpM * 32 + mf * 16 + lr) * S + kb + lc;
                a[mf][0] = __float_as_uint(p[0]);
                a[mf][2] = __float_as_uint(p[4]);
                a[mf][1] = __float_as_uint(p[8 * S]);
                a[mf][3] = __float_as_uint(p[8 * S + 4]);
            }
            #pragma unroll
            for (int nf = 0; nf < 4; nf++) {
                const float* p = sW + (warpN * 32 + nf * 8 + lr) * S + kb + lc;
                bb[nf][0] = __float_as_uint(p[0]);
                bb[nf][1] = __float_as_uint(p[4]);
            }
            #pragma unroll
            for (int mf = 0; mf < 2; mf++)
                #pragma unroll
                for (int nf = 0; nf < 4; nf++) {
                    asm volatile(
                        "mma.sync.aligned.m16n8k8.row.col.f32.tf32.tf32.f32 "
                        "{%0,%1,%2,%3}, {%4,%5,%6,%7}, {%8,%9}, {%0,%1,%2,%3};"
                        : "+f"(d[mf][nf][0]), "+f"(d[mf][nf][1]),
                          "+f"(d[mf][nf][2]), "+f"(d[mf][nf][3])
                        : "r"(a[mf][0]), "r"(a[mf][1]), "r"(a[mf][2]), "r"(a[mf][3]),
                          "r"(bb[nf][0]), "r"(bb[nf][1]));
                }
        }
        __syncthreads();

        // steal next tile, prefetch it, then do epilogue under the copies
        if (tid == 0) sTile = atomicAdd(&g_tctr[cid], 1);
        __syncthreads();
        int nxt = sTile;
        if (nxt < NTILES) {
            #pragma unroll
            for (int j = 0; j < 8; j++) {
                int idx = tid + j * 256;
                int row = idx & 63, ch = idx >> 6;
                int node = nxt * NT + row;
                const float* src = Xsrc + (size_t)(node < NN ? node : 0) * C + ch * 4;
                int sz = (node < NN) ? 16 : 0;
                asm volatile("cp.async.cg.shared.global [%0], [%1], 16, %2;"
                             :: "r"(sXaddr + (unsigned)(row * S + ch * 4) * 4), "l"(src), "r"(sz));
            }
        }
        asm volatile("cp.async.commit_group;" ::: "memory");

        // ---- epilogue ----
        #pragma unroll
        for (int mf = 0; mf < 2; mf++) {
            #pragma unroll
            for (int rr = 0; rr < 2; rr++) {
                int node = cur * NT + warpM * 32 + mf * 16 + rr * 8 + lr;
                if (node >= NN) continue;
                #pragma unroll
                for (int nf = 0; nf < 4; nf++) {
                    int o = warpN * 32 + nf * 8 + lc * 2;
                    float vx = d[mf][nf][rr * 2 + 0];
                    float vy = d[mf][nf][rr * 2 + 1];
                    size_t off = (size_t)node * C + o;
                    if (MODE == 0) {
                        vx += bias2[nf].x; vy += bias2[nf].y;
                        *(float2*)(g_y + off) = make_float2(vx, vy);
                    } else {
                        float2 y = *(const float2*)(g_y + off);
                        vx += y.x; vy += y.y;
                        if (MODE == 1) {
                            vx = fmaxf(vx, 0.0f);
                            vy = fmaxf(vy, 0.0f);
                            uint2 m = load_mask2(drop, off, m4B);
                            vx = m.x ? tf32r(vx * 2.5f) : 0.0f;
                            vy = m.y ? tf32r(vy * 2.5f) : 0.0f;
                            *(float2*)(g_h + off) = make_float2(vx, vy);
                        } else {
                            *(float2*)(outp + off) = make_float2(vx, vy);
                        }
                    }
                }
            }
        }
        cur = nxt;
    }
}

// ---------------------------------------------------------------------------
extern "C" void kernel_launch(void* const* d_in, const int* in_sizes, int n_in,
                              void* d_out, int out_size) {
    const float* x   = (const float*)d_in[0];
    const void*  ei  = d_in[1];
    const float* Wr[3] = {(const float*)d_in[2], (const float*)d_in[5], (const float*)d_in[8]};
    const float* Wo[3] = {(const float*)d_in[3], (const float*)d_in[6], (const float*)d_in[9]};
    const float* bv[3] = {(const float*)d_in[4], (const float*)d_in[7], (const float*)d_in[10]};
    const void*  dr[3] = {d_in[11], d_in[12], d_in[13]};
    float* out = (float*)d_out;

    static cudaStream_t s2 = nullptr;
    static cudaEvent_t evF = nullptr, evJ = nullptr, evI = nullptr;
    static float *p_h = nullptr, *p_agg = nullptr;
    if (!s2) {
        cudaStreamCreateWithFlags(&s2, cudaStreamNonBlocking);
        cudaEventCreateWithFlags(&evF, cudaEventDisableTiming);
        cudaEventCreateWithFlags(&evJ, cudaEventDisableTiming);
        cudaEventCreateWithFlags(&evI, cudaEventDisableTiming);
        cudaGetSymbolAddress((void**)&p_h, g_h);
        cudaGetSymbolAddress((void**)&p_agg, g_agg);
        cudaFuncSetAttribute(gemm_half<0>, cudaFuncAttributeMaxDynamicSharedMemorySize, SMEM_B);
        cudaFuncSetAttribute(gemm_half<1>, cudaFuncAttributeMaxDynamicSharedMemorySize, SMEM_B);
        cudaFuncSetAttribute(gemm_half<2>, cudaFuncAttributeMaxDynamicSharedMemorySize, SMEM_B);
    }

    const int initBlocks = (NN * (C / 4) + 255) / 256;
    const int edgeBlocks = (CE + 255) / 256;
    const int nodeBlocks = (NN + 255) / 256;
    const int gathBlocks = (NN * 32 + 255) / 256;

    sniff_kernel<<<1, 32>>>(ei, dr[0]);

    // fork: init (h) on s2, CSR build on default — independent
    cudaEventRecord(evF, 0);
    cudaStreamWaitEvent(s2, evF, 0);
    init_kernel<<<initBlocks, 256, 0, s2>>>(x, dr[0]);
    cudaEventRecord(evI, s2);

    zero_deg_kernel<<<nodeBlocks, 256>>>();
    hist_kernel<<<edgeBlocks, 256>>>(ei);
    scan_block_kernel<<<SCAN_BLOCKS, 256>>>();
    scan_tops_kernel<<<1, 256>>>();
    scan_fix_kernel<<<SCAN_BLOCKS, 256>>>();
    fill_kernel<<<edgeBlocks, 256>>>(ei);
    cudaStreamWaitEvent(0, evI, 0);   // join: h ready + CSR ready

    for (int l = 0; l < 3; l++) {
        // fork: root pass (Y = h*Wroot^T + b) runs concurrently with gather
        cudaEventRecord(evF, 0);
        cudaStreamWaitEvent(s2, evF, 0);
        gemm_half<0><<<GRID_G, 256, SMEM_B, s2>>>(Wo[l], bv[l], nullptr, p_h, nullptr, l);
        cudaEventRecord(evJ, s2);

        gather_kernel<<<gathBlocks, 256>>>();

        cudaStreamWaitEvent(0, evJ, 0);
        if (l < 2)
            gemm_half<1><<<GRID_G, 256, SMEM_B>>>(Wr[l], nullptr, dr[l + 1], p_agg, nullptr, 3 + l);
        else
            gemm_half<2><<<GRID_G, 256, SMEM_B>>>(Wr[2], nullptr, nullptr, p_agg, out, 5);
    }
}